// round 3
// baseline (speedup 1.0000x reference)
#include <cuda_runtime.h>
#include <cuda_bf16.h>

// SPPoolMean: per (B*C) row of N=H*W elements, mean-pool values sharing a
// superpixel label (labels < 512), then scatter the mean back to each position.
//
// NOTE: reference declares labels as jnp.int64, but JAX with default x64
// config materializes int32 — treat device buffer as int32.
//
// One CTA per row. Bins (sum + count) in shared memory. Pass 1: accumulate.
// Pass 2: finalize means. Pass 3: gather + write. Single kernel, no scratch.

#define NBINS 512
#define NROWS 512          // 16 * 32
#define NELEM 65536        // 256 * 256
#define BLOCK 1024

__global__ __launch_bounds__(BLOCK, 1)
void sp_pool_mean_kernel(const float* __restrict__ src,
                         const int* __restrict__ lab,
                         float* __restrict__ out)
{
    __shared__ float s_sum[NBINS];
    __shared__ int   s_cnt[NBINS];

    const int tid = threadIdx.x;
    const int row = blockIdx.x;

    if (tid < NBINS) {
        s_sum[tid] = 0.0f;
        s_cnt[tid] = 0;
    }
    __syncthreads();

    const size_t base = (size_t)row * NELEM;
    const float4* src4 = reinterpret_cast<const float4*>(src + base);
    const int4*   lab4 = reinterpret_cast<const int4*>(lab + base);

    // ---- Pass 1: scatter-add into shared bins (vectorized 4-wide) ----
    #pragma unroll 2
    for (int i = tid; i < NELEM / 4; i += BLOCK) {
        float4 v = src4[i];
        int4   l = lab4[i];
        atomicAdd(&s_sum[l.x], v.x);  atomicAdd(&s_cnt[l.x], 1);
        atomicAdd(&s_sum[l.y], v.y);  atomicAdd(&s_cnt[l.y], 1);
        atomicAdd(&s_sum[l.z], v.z);  atomicAdd(&s_cnt[l.z], 1);
        atomicAdd(&s_sum[l.w], v.w);  atomicAdd(&s_cnt[l.w], 1);
    }
    __syncthreads();

    // ---- Pass 2: bins -> means ----
    if (tid < NBINS) {
        int c = s_cnt[tid];
        s_sum[tid] = c ? (s_sum[tid] / (float)c) : 0.0f;
    }
    __syncthreads();

    // ---- Pass 3: gather means back to every position ----
    float4* out4 = reinterpret_cast<float4*>(out + base);
    #pragma unroll 2
    for (int i = tid; i < NELEM / 4; i += BLOCK) {
        int4 l = lab4[i];
        float4 r;
        r.x = s_sum[l.x];
        r.y = s_sum[l.y];
        r.z = s_sum[l.z];
        r.w = s_sum[l.w];
        out4[i] = r;
    }
}

extern "C" void kernel_launch(void* const* d_in, const int* in_sizes, int n_in,
                              void* d_out, int out_size)
{
    const float* src = (const float*)d_in[0];
    const int*   lab = (const int*)d_in[1];
    float*       out = (float*)d_out;

    sp_pool_mean_kernel<<<NROWS, BLOCK>>>(src, lab, out);
}